// round 7
// baseline (speedup 1.0000x reference)
#include <cuda_runtime.h>
#include <cuda_bf16.h>
#include <cstdint>

// dims fixed by setup_inputs
#define NN     2048
#define ABATCH 16
#define DIN    128
#define DOUT   128
#define TCHUNKS 32      // 64-row n-tiles -> 32 partials per column

// ---------------- device scratch (no allocs allowed) ----------------
__device__ float g_part[TCHUNKS * NN];
__device__ float g_rinv[NN];
__device__ __nv_bfloat16 g_adjT[(size_t)NN * NN];           // adjT[m][n], 8 MB
__device__ __nv_bfloat16 g_yT[(size_t)ABATCH * DOUT * NN];  // yT[ab][d][n], 8 MB
__device__ __nv_bfloat16 g_xb[(size_t)ABATCH * NN * DIN];   // bf16 x, 8 MB

__device__ __forceinline__ uint32_t smem_u32(const void* p) {
    return (uint32_t)__cvta_generic_to_shared(p);
}
__device__ __forceinline__ void cp_async16(uint32_t dst, const void* src) {
    asm volatile("cp.async.cg.shared.global [%0], [%1], 16;" :: "r"(dst), "l"(src));
}
__device__ __forceinline__ void cp_commit() {
    asm volatile("cp.async.commit_group;" ::: "memory");
}
template <int N>
__device__ __forceinline__ void cp_wait() {
    asm volatile("cp.async.wait_group %0;" :: "n"(N) : "memory");
}
__device__ __forceinline__ void ldsm_x4(uint32_t* r, uint32_t addr) {
    asm volatile("ldmatrix.sync.aligned.m8n8.x4.shared.b16 {%0,%1,%2,%3}, [%4];"
                 : "=r"(r[0]), "=r"(r[1]), "=r"(r[2]), "=r"(r[3]) : "r"(addr));
}
__device__ __forceinline__ void mma16816(float* d, const uint32_t* a, const uint32_t* b) {
    asm volatile(
        "mma.sync.aligned.m16n8k16.row.col.f32.bf16.bf16.f32 "
        "{%0,%1,%2,%3}, {%4,%5,%6,%7}, {%8,%9}, {%0,%1,%2,%3};"
        : "+f"(d[0]), "+f"(d[1]), "+f"(d[2]), "+f"(d[3])
        : "r"(a[0]), "r"(a[1]), "r"(a[2]), "r"(a[3]), "r"(b[0]), "r"(b[1]));
}
__device__ __forceinline__ uint32_t pack_bf2(float a, float b) {
    __nv_bfloat162 t = __floats2bfloat162_rn(a, b);
    return *(uint32_t*)&t;
}

// ============================================================
// Kernel 1: fused transpose + partial column sums (v2: 64x64 tiles)
// grid (32 m-tiles, 32 n-tiles), 256 threads
// ============================================================
__global__ void __launch_bounds__(256) transpose_colsum_kernel(const float* __restrict__ adj) {
    __shared__ float t[64][65];
    const int mx = blockIdx.x * 64, ny = blockIdx.y * 64;
    const int tid = threadIdx.x;
    const int row = tid >> 2;          // 0..63
    const int q   = tid & 3;

    // load 64x64 fp32 tile: 4 float4 per thread, coalesced
#pragma unroll
    for (int i = 0; i < 4; ++i) {
        const int f4 = q + 4 * i;      // 0..15
        float4 v = *(const float4*)&adj[(size_t)(ny + row) * NN + mx + f4 * 4];
        t[row][f4 * 4 + 0] = v.x;
        t[row][f4 * 4 + 1] = v.y;
        t[row][f4 * 4 + 2] = v.z;
        t[row][f4 * 4 + 3] = v.w;
    }
    __syncthreads();

    // transposed bf16 store + column partial sums
    const int m  = row;                // local m
    const int nq = q * 16;             // 16 n values per thread
    float vv[16];
    float s = 0.f;
#pragma unroll
    for (int j = 0; j < 16; ++j) {
        vv[j] = t[nq + j][m];
        s += vv[j];
    }
    uint4 p0, p1;
    p0.x = pack_bf2(vv[0],  vv[1]);  p0.y = pack_bf2(vv[2],  vv[3]);
    p0.z = pack_bf2(vv[4],  vv[5]);  p0.w = pack_bf2(vv[6],  vv[7]);
    p1.x = pack_bf2(vv[8],  vv[9]);  p1.y = pack_bf2(vv[10], vv[11]);
    p1.z = pack_bf2(vv[12], vv[13]); p1.w = pack_bf2(vv[14], vv[15]);
    char* dst = (char*)g_adjT + ((size_t)(mx + m) * NN + ny + nq) * 2;
    *(uint4*)dst        = p0;
    *(uint4*)(dst + 16) = p1;

    // reduce partials across the 4 q-lanes (adjacent lanes in the warp)
    s += __shfl_xor_sync(0xFFFFFFFF, s, 1);
    s += __shfl_xor_sync(0xFFFFFFFF, s, 2);
    if (q == 0) g_part[blockIdx.y * NN + mx + m] = s;
}

// ============================================================
// Kernel 2: reduce -> rinv = rsqrt(colsum)
// ============================================================
__global__ void rinv_kernel() {
    int col = blockIdx.x * 256 + threadIdx.x;
    float s = 0.f;
#pragma unroll
    for (int c = 0; c < TCHUNKS; ++c)
        s += g_part[c * NN + col];
    g_rinv[col] = rsqrtf(s);
}

// ============================================================
// Kernel 2b: convert x -> bf16 (8 elems/thread)
// ============================================================
__global__ void convx_kernel(const float* __restrict__ x) {
    size_t i = ((size_t)blockIdx.x * 256 + threadIdx.x) * 8;
    float4 v0 = *(const float4*)&x[i];
    float4 v1 = *(const float4*)&x[i + 4];
    uint4 pk;
    pk.x = pack_bf2(v0.x, v0.y);
    pk.y = pack_bf2(v0.z, v0.w);
    pk.z = pack_bf2(v1.x, v1.y);
    pk.w = pack_bf2(v1.z, v1.w);
    *(uint4*)((char*)g_xb + i * 2) = pk;
}

// ============================================================
// Kernel 3: projection via mma.sync, W converted in-kernel
//   yT[ab][d][n] = bf16( rinv[n] * sum_k W[k][d] * xb[ab][n][k] )
// A = WT[d][k] (built in smem from fp32 W), B = xb rows (n), both k-contig.
// CTA: 128d x 128n, 512 threads, 16 warps (4d x 4n), warp tile 32x32.
// grid (16 n-tiles, 16 ab).
// ============================================================
#define PATILE_B (128 * 128)     // one 64-k chunk: 128 rows x 128B = 16 KB
#define WF_PITCH 132             // fp32 staging row pitch (floats), 528B

__global__ void __launch_bounds__(512, 1)
project_mma(const float* __restrict__ w) {
    extern __shared__ char smem_raw[];
    const uint32_t sbase = (smem_u32(smem_raw) + 127) & ~127u;
    const uint32_t Ao0 = sbase;                    // WT bf16 chunks: 2 x 16KB
    const uint32_t Bo0 = sbase + 2 * PATILE_B;     // xb chunks:      2 x 16KB
    const uint32_t Wo  = sbase + 4 * PATILE_B;     // W fp32 staging: 128 x 528B

    const int tid  = threadIdx.x;
    const int wid  = tid >> 5;
    const int lane = tid & 31;
    const int warp_m = (wid & 3) * 32;     // d
    const int warp_d = (wid >> 2) * 32;    // n (local)
    const int n0 = blockIdx.x * 128;
    const int ab = blockIdx.y;

    const char* Bg = (const char*)(g_xb + ((size_t)ab * NN + n0) * DIN);

    // stage W fp32: 128 rows x 32 f4; 8 f4/thread
    {
        const int r  = tid >> 2;           // 0..127
        const int c0 = tid & 3;
#pragma unroll
        for (int i = 0; i < 8; ++i) {
            const int f4 = c0 + 4 * i;     // 0..31
            cp_async16(Wo + (uint32_t)r * (WF_PITCH * 4) + f4 * 16,
                       (const char*)w + ((size_t)r * DOUT + f4 * 4) * 4);
        }
    }
    // load both 64-k chunks of B
    {
        const int lrow = tid >> 2;
        const int lc0  = (tid & 3) * 2;
#pragma unroll
        for (int c = 0; c < 2; ++c)
#pragma unroll
            for (int i = 0; i < 2; ++i) {
                int ch = lc0 + i;
                uint32_t sw = (uint32_t)(ch ^ (lrow & 7)) * 16 + (uint32_t)lrow * 128;
                size_t goff = ((size_t)lrow * DIN + c * 64 + ch * 8) * 2;
                cp_async16(Bo0 + c * PATILE_B + sw, Bg + goff);
            }
    }
    cp_commit();
    cp_wait<0>();
    __syncthreads();

    // convert W -> WT bf16 swizzled: thread owns d = tid>>2, k-range (tid&3)*32..+31
    {
        const int d  = tid >> 2;
        const int k0 = (tid & 3) * 32;
#pragma unroll
        for (int k = 0; k < 32; k += 2) {
            const int kk = k0 + k;
            float v0, v1;
            asm volatile("ld.shared.f32 %0, [%1];" : "=f"(v0)
                         : "r"(Wo + (uint32_t)kk * (WF_PITCH * 4) + d * 4));
            asm volatile("ld.shared.f32 %0, [%1];" : "=f"(v1)
                         : "r"(Wo + (uint32_t)(kk + 1) * (WF_PITCH * 4) + d * 4));
            const int c   = kk >> 6;
            const int kl  = kk & 63;
            uint32_t addr = Ao0 + c * PATILE_B + (uint32_t)d * 128
                          + (uint32_t)((kl >> 3) ^ (d & 7)) * 16 + (kl & 7) * 2;
            uint32_t pk = pack_bf2(v0, v1);
            asm volatile("st.shared.b32 [%0], %1;" :: "r"(addr), "r"(pk));
        }
    }
    __syncthreads();

    float acc[2][4][4];
#pragma unroll
    for (int mf = 0; mf < 2; ++mf)
#pragma unroll
        for (int nf = 0; nf < 4; ++nf)
#pragma unroll
            for (int e = 0; e < 4; ++e) acc[mf][nf][e] = 0.f;

    const int portion = lane >> 3;
    const int w8 = lane & 7;

#pragma unroll
    for (int c = 0; c < 2; ++c) {
        const uint32_t Ao = Ao0 + c * PATILE_B;
        const uint32_t Bo = Bo0 + c * PATILE_B;
#pragma unroll
        for (int ks = 0; ks < 4; ++ks) {
            const int kb8 = ks * 2;
            uint32_t a[2][4], b[4][2];
#pragma unroll
            for (int mf = 0; mf < 2; ++mf) {
                int row = warp_m + mf * 16 + (portion & 1) * 8 + w8;
                int ch  = kb8 + (portion >> 1);
                ldsm_x4(a[mf], Ao + (uint32_t)row * 128 + (uint32_t)(ch ^ (row & 7)) * 16);
            }
#pragma unroll
            for (int nfp = 0; nfp < 2; ++nfp) {
                int row = warp_d + nfp * 16 + (portion >> 1) * 8 + w8;
                int ch  = kb8 + (portion & 1);
                uint32_t r[4];
                ldsm_x4(r, Bo + (uint32_t)row * 128 + (uint32_t)(ch ^ (row & 7)) * 16);
                b[2 * nfp][0]     = r[0];
                b[2 * nfp][1]     = r[1];
                b[2 * nfp + 1][0] = r[2];
                b[2 * nfp + 1][1] = r[3];
            }
#pragma unroll
            for (int mf = 0; mf < 2; ++mf)
#pragma unroll
                for (int nf = 0; nf < 4; ++nf)
                    mma16816(acc[mf][nf], a[mf], b[nf]);
        }
    }

    // epilogue: rows=d, cols=n; scale by rinv[n], store bf16 pairs to yT[ab][d][n]
    const int g  = lane >> 2;
    const int tc = lane & 3;
    char* yT = (char*)(g_yT + (size_t)ab * DOUT * NN);
#pragma unroll
    for (int mf = 0; mf < 2; ++mf) {
        const int d0g = warp_m + mf * 16 + g;
#pragma unroll
        for (int nf = 0; nf < 4; ++nf) {
            const int ng = n0 + warp_d + nf * 8 + tc * 2;
            const float rv0 = g_rinv[ng];
            const float rv1 = g_rinv[ng + 1];
            *(uint32_t*)(yT + ((size_t)d0g * NN + ng) * 2) =
                pack_bf2(acc[mf][nf][0] * rv0, acc[mf][nf][1] * rv1);
            *(uint32_t*)(yT + ((size_t)(d0g + 8) * NN + ng) * 2) =
                pack_bf2(acc[mf][nf][2] * rv0, acc[mf][nf][3] * rv1);
        }
    }
}

// ============================================================
// Kernel 4: mma.sync bf16 aggregate (4-stage cp.async + k-step frag prefetch)
//   out[ab][m][d] = relu( rinv[m] * sum_n adjT[m][n]*yT[ab][d][n] + bias[d] )
// CTA 128m x 128d, BK=64, 16 warps (4m x 4d), warp 32x32.
// grid (16 m-tiles, 16 ab), 512 threads, 128KB smem.
// ============================================================
#define BK        64
#define ATILE_B   (128 * 128)       // 16 KB
#define STAGE_B   (2 * ATILE_B)     // 32 KB
#define NSTAGES   4
#define NCHUNKS   (NN / BK)         // 32

__global__ void __launch_bounds__(512, 1)
aggregate_mma(const float* __restrict__ bias, float* __restrict__ out) {
    extern __shared__ char smem_raw[];
    const uint32_t sbase = (smem_u32(smem_raw) + 127) & ~127u;

    const int tid  = threadIdx.x;
    const int wid  = tid >> 5;
    const int lane = tid & 31;
    const int warp_m = (wid & 3) * 32;
    const int warp_d = (wid >> 2) * 32;
    const int m0   = blockIdx.x * 128;
    const int ab   = blockIdx.y;

    const char* Ag = (const char*)(g_adjT + (size_t)m0 * NN);
    const char* Bg = (const char*)(g_yT + (size_t)ab * DOUT * NN);

    const int lrow = tid >> 2;
    const int lc0  = (tid & 3) * 2;

    auto load_buf = [&](int buf, int c) {
        const uint32_t Ao = sbase + buf * STAGE_B;
        const uint32_t Bo = Ao + ATILE_B;
        const size_t rowoff = (size_t)lrow * NN + c * BK;
#pragma unroll
        for (int i = 0; i < 2; ++i) {
            int ch = lc0 + i;
            uint32_t sw = (uint32_t)(ch ^ (lrow & 7)) * 16 + (uint32_t)lrow * 128;
            const size_t goff = (rowoff + ch * 8) * 2;
            cp_async16(Ao + sw, Ag + goff);
            cp_async16(Bo + sw, Bg + goff);
        }
        cp_commit();
    };

    float acc[2][4][4];
#pragma unroll
    for (int mf = 0; mf < 2; ++mf)
#pragma unroll
        for (int nf = 0; nf < 4; ++nf)
#pragma unroll
            for (int e = 0; e < 4; ++e) acc[mf][nf][e] = 0.f;

    load_buf(0, 0);
    load_buf(1, 1);
    load_buf(2, 2);

    const int portion = lane >> 3;
    const int w8 = lane & 7;

    uint32_t afr[2][2][4], bfr[2][4][2];

    for (int c = 0; c < NCHUNKS; ++c) {
        if (c + 2 < NCHUNKS)      cp_wait<2>();
        else if (c + 1 < NCHUNKS) cp_wait<1>();
        else                      cp_wait<0>();
        __syncthreads();
        if (c + 3 < NCHUNKS) load_buf((c + 3) & 3, c + 3);

        const uint32_t Ao = sbase + (c & 3) * STAGE_B;
        const uint32_t Bo = Ao + ATILE_B;

        auto ldfrag = [&](int ks, uint32_t (&a)[2][4], uint32_t (&b)[4][2]) {
            const int kb8 = ks * 2;
#pragma unroll
            for (int mf = 0; mf < 2; ++mf) {
                int row = warp_m + mf * 16 + (portion & 1) * 8 + w8;
                int ch  = kb8 + (portion >> 1);
                ldsm_x4(a[mf], Ao + (uint32_t)row * 128 + (uint32_t)(ch ^ (row & 7)) * 16);
            }
#pragma unroll
            for (int nfp = 0; nfp < 2; ++nfp) {
                int row = warp_d + nfp * 16 + (portion >> 1) * 8 + w8;
                int ch  = kb8 + (portion & 1);
                uint32_t r[4];
                ldsm_x4(r, Bo + (uint32_t)row * 128 + (uint32_t)(ch ^ (row & 7)) * 16);
                b[2 * nfp][0]     = r[0];
                b[2 * nfp][1]     = r[1];
                b[2 * nfp + 1][0] = r[2];
                b[2 * nfp + 1][1] = r[3];
            }
        };

        ldfrag(0, afr[0], bfr[0]);
#pragma unroll
        for (int ks = 0; ks < 4; ++ks) {
            const int cur = ks & 1;
            if (ks < 3) ldfrag(ks + 1, afr[cur ^ 1], bfr[cur ^ 1]);
#pragma unroll
            for (int mf = 0; mf < 2; ++mf)
#pragma unroll
                for (int nf = 0; nf < 4; ++nf)
                    mma16816(acc[mf][nf], afr[cur][mf], bfr[cur][nf]);
        }
    }

    // epilogue: rinv[m] * acc + bias[d], relu
    const int g  = lane >> 2;
    const int tc = lane & 3;
    float* outab = out + (size_t)ab * NN * DOUT;
#pragma unroll
    for (int mf = 0; mf < 2; ++mf) {
        const int mrow0 = m0 + warp_m + mf * 16 + g;
        const float rv0 = g_rinv[mrow0];
        const float rv1 = g_rinv[mrow0 + 8];
#pragma unroll
        for (int nf = 0; nf < 4; ++nf) {
            const int d0 = warp_d + nf * 8 + tc * 2;
            const float b0 = __ldg(&bias[d0]);
            const float b1 = __ldg(&bias[d0 + 1]);
            float2 v0, v1;
            v0.x = fmaxf(fmaf(acc[mf][nf][0], rv0, b0), 0.f);
            v0.y = fmaxf(fmaf(acc[mf][nf][1], rv0, b1), 0.f);
            v1.x = fmaxf(fmaf(acc[mf][nf][2], rv1, b0), 0.f);
            v1.y = fmaxf(fmaf(acc[mf][nf][3], rv1, b1), 0.f);
            *(float2*)&outab[(size_t)mrow0 * DOUT + d0]       = v0;
            *(float2*)&outab[(size_t)(mrow0 + 8) * DOUT + d0] = v1;
        }
    }
}

// ============================================================
extern "C" void kernel_launch(void* const* d_in, const int* in_sizes, int n_in,
                              void* d_out, int out_size) {
    const float* adj  = (const float*)d_in[0];
    const float* x    = (const float*)d_in[1];
    const float* w    = (const float*)d_in[2];
    const float* bias = (const float*)d_in[3];
    float* out        = (float*)d_out;

    const int agg_smem  = NSTAGES * STAGE_B + 256;            // 128 KB + slack
    const int proj_smem = 4 * PATILE_B + 128 * WF_PITCH * 4 + 256;  // 64K + 67.5K + slack
    cudaFuncSetAttribute(aggregate_mma, cudaFuncAttributeMaxDynamicSharedMemorySize, agg_smem);
    cudaFuncSetAttribute(project_mma, cudaFuncAttributeMaxDynamicSharedMemorySize, proj_smem);

    transpose_colsum_kernel<<<dim3(32, 32), 256>>>(adj);
    rinv_kernel<<<NN / 256, 256>>>();
    convx_kernel<<<(ABATCH * NN * DIN) / (256 * 8), 256>>>(x);
    project_mma<<<dim3(16, 16), 512, proj_smem>>>(w);
    aggregate_mma<<<dim3(16, 16), 512, agg_smem>>>(bias, out);
}

// round 8
// speedup vs baseline: 1.0438x; 1.0438x over previous
#include <cuda_runtime.h>
#include <cuda_bf16.h>
#include <cstdint>

// dims fixed by setup_inputs
#define NN     2048
#define ABATCH 16
#define DIN    128
#define DOUT   128
#define TCHUNKS 32      // 64-row n-tiles -> 32 partials per column

// ---------------- device scratch (no allocs allowed) ----------------
__device__ float g_part[TCHUNKS * NN];
__device__ float g_rinv[NN];
__device__ __nv_bfloat16 g_adjT[(size_t)NN * NN];           // adjT[m][n], 8 MB
__device__ __nv_bfloat16 g_yT[(size_t)ABATCH * DOUT * NN];  // yT[ab][d][n], 8 MB
__device__ __nv_bfloat16 g_xb[(size_t)ABATCH * NN * DIN];   // bf16 x, 8 MB
__device__ __nv_bfloat16 g_wt[DOUT * DIN];                  // WT[d][k] bf16

__device__ __forceinline__ uint32_t smem_u32(const void* p) {
    return (uint32_t)__cvta_generic_to_shared(p);
}
__device__ __forceinline__ void cp_async16(uint32_t dst, const void* src) {
    asm volatile("cp.async.cg.shared.global [%0], [%1], 16;" :: "r"(dst), "l"(src));
}
__device__ __forceinline__ void cp_commit() {
    asm volatile("cp.async.commit_group;" ::: "memory");
}
template <int N>
__device__ __forceinline__ void cp_wait() {
    asm volatile("cp.async.wait_group %0;" :: "n"(N) : "memory");
}
__device__ __forceinline__ void ldsm_x4(uint32_t* r, uint32_t addr) {
    asm volatile("ldmatrix.sync.aligned.m8n8.x4.shared.b16 {%0,%1,%2,%3}, [%4];"
                 : "=r"(r[0]), "=r"(r[1]), "=r"(r[2]), "=r"(r[3]) : "r"(addr));
}
__device__ __forceinline__ void mma16816(float* d, const uint32_t* a, const uint32_t* b) {
    asm volatile(
        "mma.sync.aligned.m16n8k16.row.col.f32.bf16.bf16.f32 "
        "{%0,%1,%2,%3}, {%4,%5,%6,%7}, {%8,%9}, {%0,%1,%2,%3};"
        : "+f"(d[0]), "+f"(d[1]), "+f"(d[2]), "+f"(d[3])
        : "r"(a[0]), "r"(a[1]), "r"(a[2]), "r"(a[3]), "r"(b[0]), "r"(b[1]));
}
__device__ __forceinline__ uint32_t pack_bf2(float a, float b) {
    __nv_bfloat162 t = __floats2bfloat162_rn(a, b);
    return *(uint32_t*)&t;
}

// ============================================================
// Kernel 1: fused transpose + partial column sums (64x64 tiles)
// grid (32 m-tiles, 32 n-tiles), 256 threads
// ============================================================
__global__ void __launch_bounds__(256) transpose_colsum_kernel(const float* __restrict__ adj) {
    __shared__ float t[64][65];
    const int mx = blockIdx.x * 64, ny = blockIdx.y * 64;
    const int tid = threadIdx.x;
    const int row = tid >> 2;          // 0..63
    const int q   = tid & 3;

#pragma unroll
    for (int i = 0; i < 4; ++i) {
        const int f4 = q + 4 * i;      // 0..15
        float4 v = *(const float4*)&adj[(size_t)(ny + row) * NN + mx + f4 * 4];
        t[row][f4 * 4 + 0] = v.x;
        t[row][f4 * 4 + 1] = v.y;
        t[row][f4 * 4 + 2] = v.z;
        t[row][f4 * 4 + 3] = v.w;
    }
    __syncthreads();

    const int m  = row;
    const int nq = q * 16;
    float vv[16];
    float s = 0.f;
#pragma unroll
    for (int j = 0; j < 16; ++j) {
        vv[j] = t[nq + j][m];
        s += vv[j];
    }
    uint4 p0, p1;
    p0.x = pack_bf2(vv[0],  vv[1]);  p0.y = pack_bf2(vv[2],  vv[3]);
    p0.z = pack_bf2(vv[4],  vv[5]);  p0.w = pack_bf2(vv[6],  vv[7]);
    p1.x = pack_bf2(vv[8],  vv[9]);  p1.y = pack_bf2(vv[10], vv[11]);
    p1.z = pack_bf2(vv[12], vv[13]); p1.w = pack_bf2(vv[14], vv[15]);
    char* dst = (char*)g_adjT + ((size_t)(mx + m) * NN + ny + nq) * 2;
    *(uint4*)dst        = p0;
    *(uint4*)(dst + 16) = p1;

    s += __shfl_xor_sync(0xFFFFFFFF, s, 1);
    s += __shfl_xor_sync(0xFFFFFFFF, s, 2);
    if (q == 0) g_part[blockIdx.y * NN + mx + m] = s;
}

// ============================================================
// Kernel 2: reduce -> rinv = rsqrt(colsum)
// ============================================================
__global__ void rinv_kernel() {
    int col = blockIdx.x * 256 + threadIdx.x;
    float s = 0.f;
#pragma unroll
    for (int c = 0; c < TCHUNKS; ++c)
        s += g_part[c * NN + col];
    g_rinv[col] = rsqrtf(s);
}

// ============================================================
// Kernel 2b: convert x -> bf16 (8 elems/thread); last 8 blocks also build
//            WT[d][k] = bf16(W[k][d])
// grid = 2048 + 8 blocks, 256 threads
// ============================================================
#define CONVX_BLOCKS ((ABATCH * NN * DIN) / (256 * 8))   // 2048

__global__ void convx_kernel(const float* __restrict__ x, const float* __restrict__ w) {
    if (blockIdx.x < CONVX_BLOCKS) {
        size_t i = ((size_t)blockIdx.x * 256 + threadIdx.x) * 8;
        float4 v0 = *(const float4*)&x[i];
        float4 v1 = *(const float4*)&x[i + 4];
        uint4 pk;
        pk.x = pack_bf2(v0.x, v0.y);
        pk.y = pack_bf2(v0.z, v0.w);
        pk.z = pack_bf2(v1.x, v1.y);
        pk.w = pack_bf2(v1.z, v1.w);
        *(uint4*)((char*)g_xb + i * 2) = pk;
    } else {
        // W transpose: 8 blocks x 256 threads x 8 elems = 16384
        int idx = ((blockIdx.x - CONVX_BLOCKS) * 256 + threadIdx.x) * 8;
        int d  = idx >> 7;
        int k0 = idx & 127;
        uint4 pk;
        float a0 = w[(size_t)(k0 + 0) * DOUT + d], a1 = w[(size_t)(k0 + 1) * DOUT + d];
        float a2 = w[(size_t)(k0 + 2) * DOUT + d], a3 = w[(size_t)(k0 + 3) * DOUT + d];
        float a4 = w[(size_t)(k0 + 4) * DOUT + d], a5 = w[(size_t)(k0 + 5) * DOUT + d];
        float a6 = w[(size_t)(k0 + 6) * DOUT + d], a7 = w[(size_t)(k0 + 7) * DOUT + d];
        pk.x = pack_bf2(a0, a1);
        pk.y = pack_bf2(a2, a3);
        pk.z = pack_bf2(a4, a5);
        pk.w = pack_bf2(a6, a7);
        *(uint4*)((char*)g_wt + (size_t)idx * 2) = pk;
    }
}

// ============================================================
// Kernel 3: projection via mma.sync (single-shot, K=128 in 2 chunks of 64)
//   yT[ab][d][n] = bf16( rinv[n] * sum_k WT[d][k] * xb[ab][n][k] )
// A = WT rows (d), B = xb rows (n), both k-contig -> plain ldmatrix.
// CTA: 128d x 128n, 512 threads, 16 warps (4d x 4n), warp tile 32x32.
// grid (16 n-tiles, 16 ab).
// ============================================================
#define PATILE_B (128 * 128)   // one 64-k chunk: 128 rows x 128B = 16 KB

__global__ void __launch_bounds__(512, 1)
project_mma() {
    extern __shared__ char smem_raw[];
    const uint32_t sbase = (smem_u32(smem_raw) + 127) & ~127u;
    const uint32_t Ao0 = sbase;                    // WT chunks: 2 x 16KB
    const uint32_t Bo0 = sbase + 2 * PATILE_B;     // xb chunks: 2 x 16KB

    const int tid  = threadIdx.x;
    const int wid  = tid >> 5;
    const int lane = tid & 31;
    const int warp_m = (wid & 3) * 32;     // d
    const int warp_d = (wid >> 2) * 32;    // n (local)
    const int n0 = blockIdx.x * 128;
    const int ab = blockIdx.y;

    const char* Ag = (const char*)g_wt;
    const char* Bg = (const char*)(g_xb + ((size_t)ab * NN + n0) * DIN);

    const int lrow = tid >> 2;          // 0..127
    const int lc0  = (tid & 3) * 2;
#pragma unroll
    for (int c = 0; c < 2; ++c) {
#pragma unroll
        for (int i = 0; i < 2; ++i) {
            int ch = lc0 + i;
            uint32_t sw = (uint32_t)(ch ^ (lrow & 7)) * 16 + (uint32_t)lrow * 128;
            size_t goff = ((size_t)lrow * DIN + c * 64 + ch * 8) * 2;
            cp_async16(Ao0 + c * PATILE_B + sw, Ag + goff);
            cp_async16(Bo0 + c * PATILE_B + sw, Bg + goff);
        }
    }
    cp_commit();
    cp_wait<0>();
    __syncthreads();

    float acc[2][4][4];
#pragma unroll
    for (int mf = 0; mf < 2; ++mf)
#pragma unroll
        for (int nf = 0; nf < 4; ++nf)
#pragma unroll
            for (int e = 0; e < 4; ++e) acc[mf][nf][e] = 0.f;

    const int portion = lane >> 3;
    const int w8 = lane & 7;

#pragma unroll
    for (int c = 0; c < 2; ++c) {
        const uint32_t Ao = Ao0 + c * PATILE_B;
        const uint32_t Bo = Bo0 + c * PATILE_B;
#pragma unroll
        for (int ks = 0; ks < 4; ++ks) {
            const int kb8 = ks * 2;
            uint32_t a[2][4], b[4][2];
#pragma unroll
            for (int mf = 0; mf < 2; ++mf) {
                int row = warp_m + mf * 16 + (portion & 1) * 8 + w8;
                int ch  = kb8 + (portion >> 1);
                ldsm_x4(a[mf], Ao + (uint32_t)row * 128 + (uint32_t)(ch ^ (row & 7)) * 16);
            }
#pragma unroll
            for (int nfp = 0; nfp < 2; ++nfp) {
                int row = warp_d + nfp * 16 + (portion >> 1) * 8 + w8;
                int ch  = kb8 + (portion & 1);
                uint32_t r[4];
                ldsm_x4(r, Bo + (uint32_t)row * 128 + (uint32_t)(ch ^ (row & 7)) * 16);
                b[2 * nfp][0]     = r[0];
                b[2 * nfp][1]     = r[1];
                b[2 * nfp + 1][0] = r[2];
                b[2 * nfp + 1][1] = r[3];
            }
#pragma unroll
            for (int mf = 0; mf < 2; ++mf)
#pragma unroll
                for (int nf = 0; nf < 4; ++nf)
                    mma16816(acc[mf][nf], a[mf], b[nf]);
        }
    }

    const int g  = lane >> 2;
    const int tc = lane & 3;
    char* yT = (char*)(g_yT + (size_t)ab * DOUT * NN);
#pragma unroll
    for (int mf = 0; mf < 2; ++mf) {
        const int d0g = warp_m + mf * 16 + g;
#pragma unroll
        for (int nf = 0; nf < 4; ++nf) {
            const int ng = n0 + warp_d + nf * 8 + tc * 2;
            const float rv0 = g_rinv[ng];
            const float rv1 = g_rinv[ng + 1];
            *(uint32_t*)(yT + ((size_t)d0g * NN + ng) * 2) =
                pack_bf2(acc[mf][nf][0] * rv0, acc[mf][nf][1] * rv1);
            *(uint32_t*)(yT + ((size_t)(d0g + 8) * NN + ng) * 2) =
                pack_bf2(acc[mf][nf][2] * rv0, acc[mf][nf][3] * rv1);
        }
    }
}

// ============================================================
// Kernel 4: mma.sync bf16 aggregate (4-stage cp.async + k-step frag prefetch)
//   out[ab][m][d] = relu( rinv[m] * sum_n adjT[m][n]*yT[ab][d][n] + bias[d] )
// CTA 128m x 128d, BK=64, 16 warps (4m x 4d), warp 32x32.
// grid (16 m-tiles, 16 ab), 512 threads, 128KB smem.
// ============================================================
#define BK        64
#define ATILE_B   (128 * 128)       // 16 KB
#define STAGE_B   (2 * ATILE_B)     // 32 KB
#define NSTAGES   4
#define NCHUNKS   (NN / BK)         // 32

__global__ void __launch_bounds__(512, 1)
aggregate_mma(const float* __restrict__ bias, float* __restrict__ out) {
    extern __shared__ char smem_raw[];
    const uint32_t sbase = (smem_u32(smem_raw) + 127) & ~127u;

    const int tid  = threadIdx.x;
    const int wid  = tid >> 5;
    const int lane = tid & 31;
    const int warp_m = (wid & 3) * 32;
    const int warp_d = (wid >> 2) * 32;
    const int m0   = blockIdx.x * 128;
    const int ab   = blockIdx.y;

    const char* Ag = (const char*)(g_adjT + (size_t)m0 * NN);
    const char* Bg = (const char*)(g_yT + (size_t)ab * DOUT * NN);

    const int lrow = tid >> 2;
    const int lc0  = (tid & 3) * 2;

    auto load_buf = [&](int buf, int c) {
        const uint32_t Ao = sbase + buf * STAGE_B;
        const uint32_t Bo = Ao + ATILE_B;
        const size_t rowoff = (size_t)lrow * NN + c * BK;
#pragma unroll
        for (int i = 0; i < 2; ++i) {
            int ch = lc0 + i;
            uint32_t sw = (uint32_t)(ch ^ (lrow & 7)) * 16 + (uint32_t)lrow * 128;
            const size_t goff = (rowoff + ch * 8) * 2;
            cp_async16(Ao + sw, Ag + goff);
            cp_async16(Bo + sw, Bg + goff);
        }
        cp_commit();
    };

    float acc[2][4][4];
#pragma unroll
    for (int mf = 0; mf < 2; ++mf)
#pragma unroll
        for (int nf = 0; nf < 4; ++nf)
#pragma unroll
            for (int e = 0; e < 4; ++e) acc[mf][nf][e] = 0.f;

    load_buf(0, 0);
    load_buf(1, 1);
    load_buf(2, 2);

    const int portion = lane >> 3;
    const int w8 = lane & 7;

    uint32_t afr[2][2][4], bfr[2][4][2];

    for (int c = 0; c < NCHUNKS; ++c) {
        if (c + 2 < NCHUNKS)      cp_wait<2>();
        else if (c + 1 < NCHUNKS) cp_wait<1>();
        else                      cp_wait<0>();
        __syncthreads();
        if (c + 3 < NCHUNKS) load_buf((c + 3) & 3, c + 3);

        const uint32_t Ao = sbase + (c & 3) * STAGE_B;
        const uint32_t Bo = Ao + ATILE_B;

        auto ldfrag = [&](int ks, uint32_t (&a)[2][4], uint32_t (&b)[4][2]) {
            const int kb8 = ks * 2;
#pragma unroll
            for (int mf = 0; mf < 2; ++mf) {
                int row = warp_m + mf * 16 + (portion & 1) * 8 + w8;
                int ch  = kb8 + (portion >> 1);
                ldsm_x4(a[mf], Ao + (uint32_t)row * 128 + (uint32_t)(ch ^ (row & 7)) * 16);
            }
#pragma unroll
            for (int nfp = 0; nfp < 2; ++nfp) {
                int row = warp_d + nfp * 16 + (portion >> 1) * 8 + w8;
                int ch  = kb8 + (portion & 1);
                uint32_t r[4];
                ldsm_x4(r, Bo + (uint32_t)row * 128 + (uint32_t)(ch ^ (row & 7)) * 16);
                b[2 * nfp][0]     = r[0];
                b[2 * nfp][1]     = r[1];
                b[2 * nfp + 1][0] = r[2];
                b[2 * nfp + 1][1] = r[3];
            }
        };

        ldfrag(0, afr[0], bfr[0]);
#pragma unroll
        for (int ks = 0; ks < 4; ++ks) {
            const int cur = ks & 1;
            if (ks < 3) ldfrag(ks + 1, afr[cur ^ 1], bfr[cur ^ 1]);
#pragma unroll
            for (int mf = 0; mf < 2; ++mf)
#pragma unroll
                for (int nf = 0; nf < 4; ++nf)
                    mma16816(acc[mf][nf], afr[cur][mf], bfr[cur][nf]);
        }
    }

    const int g  = lane >> 2;
    const int tc = lane & 3;
    float* outab = out + (size_t)ab * NN * DOUT;
#pragma unroll
    for (int mf = 0; mf < 2; ++mf) {
        const int mrow0 = m0 + warp_m + mf * 16 + g;
        const float rv0 = g_rinv[mrow0];
        const float rv1 = g_rinv[mrow0 + 8];
#pragma unroll
        for (int nf = 0; nf < 4; ++nf) {
            const int d0 = warp_d + nf * 8 + tc * 2;
            const float b0 = __ldg(&bias[d0]);
            const float b1 = __ldg(&bias[d0 + 1]);
            float2 v0, v1;
            v0.x = fmaxf(fmaf(acc[mf][nf][0], rv0, b0), 0.f);
            v0.y = fmaxf(fmaf(acc[mf][nf][1], rv0, b1), 0.f);
            v1.x = fmaxf(fmaf(acc[mf][nf][2], rv1, b0), 0.f);
            v1.y = fmaxf(fmaf(acc[mf][nf][3], rv1, b1), 0.f);
            *(float2*)&outab[(size_t)mrow0 * DOUT + d0]       = v0;
            *(float2*)&outab[(size_t)(mrow0 + 8) * DOUT + d0] = v1;
        }
    }
}

// ============================================================
extern "C" void kernel_launch(void* const* d_in, const int* in_sizes, int n_in,
                              void* d_out, int out_size) {
    const float* adj  = (const float*)d_in[0];
    const float* x    = (const float*)d_in[1];
    const float* w    = (const float*)d_in[2];
    const float* bias = (const float*)d_in[3];
    float* out        = (float*)d_out;

    const int agg_smem  = NSTAGES * STAGE_B + 256;   // 128 KB + slack
    const int proj_smem = 4 * PATILE_B + 256;        // 64 KB + slack
    cudaFuncSetAttribute(aggregate_mma, cudaFuncAttributeMaxDynamicSharedMemorySize, agg_smem);
    cudaFuncSetAttribute(project_mma, cudaFuncAttributeMaxDynamicSharedMemorySize, proj_smem);

    transpose_colsum_kernel<<<dim3(32, 32), 256>>>(adj);
    rinv_kernel<<<NN / 256, 256>>>();
    convx_kernel<<<CONVX_BLOCKS + 8, 256>>>(x, w);
    project_mma<<<dim3(16, 16), 512, proj_smem>>>();
    aggregate_mma<<<dim3(16, 16), 512, agg_smem>>>(bias, out);
}

// round 9
// speedup vs baseline: 1.0449x; 1.0010x over previous
#include <cuda_runtime.h>
#include <cuda_bf16.h>
#include <cstdint>

// dims fixed by setup_inputs
#define NN     2048
#define ABATCH 16
#define DIN    128
#define DOUT   128
#define TCHUNKS 32

// ---------------- device scratch (no allocs allowed) ----------------
__device__ float g_part[TCHUNKS * NN];
__device__ float g_rinv[NN];
__device__ __nv_bfloat16 g_adjT[(size_t)NN * NN];           // adjT[m][n], 8 MB
__device__ __nv_bfloat16 g_yT[(size_t)ABATCH * DOUT * NN];  // yT[ab][d][n], 8 MB
__device__ __nv_bfloat16 g_xb[(size_t)ABATCH * NN * DIN];   // bf16 x, 8 MB
__device__ __nv_bfloat16 g_wt[DOUT * DIN];                  // WT[d][k] bf16

__device__ __forceinline__ uint32_t smem_u32(const void* p) {
    return (uint32_t)__cvta_generic_to_shared(p);
}
__device__ __forceinline__ void cp_async16(uint32_t dst, const void* src) {
    asm volatile("cp.async.cg.shared.global [%0], [%1], 16;" :: "r"(dst), "l"(src));
}
__device__ __forceinline__ void cp_commit() {
    asm volatile("cp.async.commit_group;" ::: "memory");
}
template <int N>
__device__ __forceinline__ void cp_wait() {
    asm volatile("cp.async.wait_group %0;" :: "n"(N) : "memory");
}
__device__ __forceinline__ void ldsm_x4(uint32_t* r, uint32_t addr) {
    asm volatile("ldmatrix.sync.aligned.m8n8.x4.shared.b16 {%0,%1,%2,%3}, [%4];"
                 : "=r"(r[0]), "=r"(r[1]), "=r"(r[2]), "=r"(r[3]) : "r"(addr));
}
__device__ __forceinline__ void mma16816(float* d, const uint32_t* a, const uint32_t* b) {
    asm volatile(
        "mma.sync.aligned.m16n8k16.row.col.f32.bf16.bf16.f32 "
        "{%0,%1,%2,%3}, {%4,%5,%6,%7}, {%8,%9}, {%0,%1,%2,%3};"
        : "+f"(d[0]), "+f"(d[1]), "+f"(d[2]), "+f"(d[3])
        : "r"(a[0]), "r"(a[1]), "r"(a[2]), "r"(a[3]), "r"(b[0]), "r"(b[1]));
}
__device__ __forceinline__ uint32_t pack_bf2(float a, float b) {
    __nv_bfloat162 t = __floats2bfloat162_rn(a, b);
    return *(uint32_t*)&t;
}

// ============================================================
// Kernel 1: fused transpose + partial column sums (64x64 tiles)
// ============================================================
__global__ void __launch_bounds__(256) transpose_colsum_kernel(const float* __restrict__ adj) {
    __shared__ float t[64][65];
    const int mx = blockIdx.x * 64, ny = blockIdx.y * 64;
    const int tid = threadIdx.x;
    const int row = tid >> 2;
    const int q   = tid & 3;

#pragma unroll
    for (int i = 0; i < 4; ++i) {
        const int f4 = q + 4 * i;
        float4 v = *(const float4*)&adj[(size_t)(ny + row) * NN + mx + f4 * 4];
        t[row][f4 * 4 + 0] = v.x;
        t[row][f4 * 4 + 1] = v.y;
        t[row][f4 * 4 + 2] = v.z;
        t[row][f4 * 4 + 3] = v.w;
    }
    __syncthreads();

    const int m  = row;
    const int nq = q * 16;
    float vv[16];
    float s = 0.f;
#pragma unroll
    for (int j = 0; j < 16; ++j) {
        vv[j] = t[nq + j][m];
        s += vv[j];
    }
    uint4 p0, p1;
    p0.x = pack_bf2(vv[0],  vv[1]);  p0.y = pack_bf2(vv[2],  vv[3]);
    p0.z = pack_bf2(vv[4],  vv[5]);  p0.w = pack_bf2(vv[6],  vv[7]);
    p1.x = pack_bf2(vv[8],  vv[9]);  p1.y = pack_bf2(vv[10], vv[11]);
    p1.z = pack_bf2(vv[12], vv[13]); p1.w = pack_bf2(vv[14], vv[15]);
    char* dst = (char*)g_adjT + ((size_t)(mx + m) * NN + ny + nq) * 2;
    *(uint4*)dst        = p0;
    *(uint4*)(dst + 16) = p1;

    s += __shfl_xor_sync(0xFFFFFFFF, s, 1);
    s += __shfl_xor_sync(0xFFFFFFFF, s, 2);
    if (q == 0) g_part[blockIdx.y * NN + mx + m] = s;
}

// ============================================================
// Kernel 2: reduce -> rinv = rsqrt(colsum)
// ============================================================
__global__ void rinv_kernel() {
    int col = blockIdx.x * 256 + threadIdx.x;
    float s = 0.f;
#pragma unroll
    for (int c = 0; c < TCHUNKS; ++c)
        s += g_part[c * NN + col];
    g_rinv[col] = rsqrtf(s);
}

// ============================================================
// Kernel 2b: convert x -> bf16; last 8 blocks build WT[d][k] = bf16(W[k][d])
// ============================================================
#define CONVX_BLOCKS ((ABATCH * NN * DIN) / (256 * 8))   // 2048

__global__ void convx_kernel(const float* __restrict__ x, const float* __restrict__ w) {
    if (blockIdx.x < CONVX_BLOCKS) {
        size_t i = ((size_t)blockIdx.x * 256 + threadIdx.x) * 8;
        float4 v0 = *(const float4*)&x[i];
        float4 v1 = *(const float4*)&x[i + 4];
        uint4 pk;
        pk.x = pack_bf2(v0.x, v0.y);
        pk.y = pack_bf2(v0.z, v0.w);
        pk.z = pack_bf2(v1.x, v1.y);
        pk.w = pack_bf2(v1.z, v1.w);
        *(uint4*)((char*)g_xb + i * 2) = pk;
    } else {
        int idx = ((blockIdx.x - CONVX_BLOCKS) * 256 + threadIdx.x) * 8;
        int d  = idx >> 7;
        int k0 = idx & 127;
        uint4 pk;
        float a0 = w[(size_t)(k0 + 0) * DOUT + d], a1 = w[(size_t)(k0 + 1) * DOUT + d];
        float a2 = w[(size_t)(k0 + 2) * DOUT + d], a3 = w[(size_t)(k0 + 3) * DOUT + d];
        float a4 = w[(size_t)(k0 + 4) * DOUT + d], a5 = w[(size_t)(k0 + 5) * DOUT + d];
        float a6 = w[(size_t)(k0 + 6) * DOUT + d], a7 = w[(size_t)(k0 + 7) * DOUT + d];
        pk.x = pack_bf2(a0, a1);
        pk.y = pack_bf2(a2, a3);
        pk.z = pack_bf2(a4, a5);
        pk.w = pack_bf2(a6, a7);
        *(uint4*)((char*)g_wt + (size_t)idx * 2) = pk;
    }
}

// ============================================================
// Kernel 3: projection via mma.sync (v3: 64d x 128n CTAs, 2 CTAs/SM)
//   yT[ab][d][n] = bf16( rinv[n] * sum_k WT[d][k] * xb[ab][n][k] )
// 256 threads, 8 warps (2d x 4n), warp tile 32x32.
// grid (16 n-tiles, 16 ab, 2 d-tiles).
// ============================================================
#define PA_CH_B  (64 * 128)     // A chunk tile: 64 rows x 128B = 8 KB
#define PB_CH_B  (128 * 128)    // B chunk tile: 128 rows x 128B = 16 KB

__global__ void __launch_bounds__(256, 2)
project_mma() {
    extern __shared__ char smem_raw[];
    const uint32_t sbase = (smem_u32(smem_raw) + 127) & ~127u;
    const uint32_t Ao0 = sbase;                   // A: 2 chunks x 8KB
    const uint32_t Bo0 = sbase + 2 * PA_CH_B;     // B: 2 chunks x 16KB

    const int tid  = threadIdx.x;
    const int wid  = tid >> 5;
    const int lane = tid & 31;
    const int warp_m = (wid & 1) * 32;     // d (local, 0..63)
    const int warp_d = (wid >> 1) * 32;    // n (local)
    const int n0 = blockIdx.x * 128;
    const int ab = blockIdx.y;
    const int dt = blockIdx.z;             // d-tile 0/1

    const char* Ag = (const char*)(g_wt + (size_t)dt * 64 * DIN);
    const char* Bg = (const char*)(g_xb + ((size_t)ab * NN + n0) * DIN);

    // A: 64 rows, 4 threads/row covering 8 chunks; 2 f4/thread/chunk-tile
    {
        const int r = tid >> 2;            // 0..63
        const int q = (tid & 3) * 2;
#pragma unroll
        for (int c = 0; c < 2; ++c)
#pragma unroll
            for (int i = 0; i < 2; ++i) {
                int ch = q + i;
                uint32_t sw = (uint32_t)(ch ^ (r & 7)) * 16 + (uint32_t)r * 128;
                size_t goff = ((size_t)r * DIN + c * 64 + ch * 8) * 2;
                cp_async16(Ao0 + c * PA_CH_B + sw, Ag + goff);
            }
    }
    // B: 128 rows, 2 threads/row covering 8 chunks; 4 f4/thread/chunk-tile
    {
        const int r = tid >> 1;            // 0..127
        const int q = (tid & 1) * 4;
#pragma unroll
        for (int c = 0; c < 2; ++c)
#pragma unroll
            for (int i = 0; i < 4; ++i) {
                int ch = q + i;
                uint32_t sw = (uint32_t)(ch ^ (r & 7)) * 16 + (uint32_t)r * 128;
                size_t goff = ((size_t)r * DIN + c * 64 + ch * 8) * 2;
                cp_async16(Bo0 + c * PB_CH_B + sw, Bg + goff);
            }
    }
    cp_commit();
    cp_wait<0>();
    __syncthreads();

    float acc[2][4][4];
#pragma unroll
    for (int mf = 0; mf < 2; ++mf)
#pragma unroll
        for (int nf = 0; nf < 4; ++nf)
#pragma unroll
            for (int e = 0; e < 4; ++e) acc[mf][nf][e] = 0.f;

    const int portion = lane >> 3;
    const int w8 = lane & 7;

#pragma unroll
    for (int c = 0; c < 2; ++c) {
        const uint32_t Ao = Ao0 + c * PA_CH_B;
        const uint32_t Bo = Bo0 + c * PB_CH_B;
#pragma unroll
        for (int ks = 0; ks < 4; ++ks) {
            const int kb8 = ks * 2;
            uint32_t a[2][4], b[4][2];
#pragma unroll
            for (int mf = 0; mf < 2; ++mf) {
                int row = warp_m + mf * 16 + (portion & 1) * 8 + w8;
                int ch  = kb8 + (portion >> 1);
                ldsm_x4(a[mf], Ao + (uint32_t)row * 128 + (uint32_t)(ch ^ (row & 7)) * 16);
            }
#pragma unroll
            for (int nfp = 0; nfp < 2; ++nfp) {
                int row = warp_d + nfp * 16 + (portion >> 1) * 8 + w8;
                int ch  = kb8 + (portion & 1);
                uint32_t r[4];
                ldsm_x4(r, Bo + (uint32_t)row * 128 + (uint32_t)(ch ^ (row & 7)) * 16);
                b[2 * nfp][0]     = r[0];
                b[2 * nfp][1]     = r[1];
                b[2 * nfp + 1][0] = r[2];
                b[2 * nfp + 1][1] = r[3];
            }
#pragma unroll
            for (int mf = 0; mf < 2; ++mf)
#pragma unroll
                for (int nf = 0; nf < 4; ++nf)
                    mma16816(acc[mf][nf], a[mf], b[nf]);
        }
    }

    const int g  = lane >> 2;
    const int tc = lane & 3;
    char* yT = (char*)(g_yT + (size_t)ab * DOUT * NN);
#pragma unroll
    for (int mf = 0; mf < 2; ++mf) {
        const int d0g = dt * 64 + warp_m + mf * 16 + g;
#pragma unroll
        for (int nf = 0; nf < 4; ++nf) {
            const int ng = n0 + warp_d + nf * 8 + tc * 2;
            const float rv0 = g_rinv[ng];
            const float rv1 = g_rinv[ng + 1];
            *(uint32_t*)(yT + ((size_t)d0g * NN + ng) * 2) =
                pack_bf2(acc[mf][nf][0] * rv0, acc[mf][nf][1] * rv1);
            *(uint32_t*)(yT + ((size_t)(d0g + 8) * NN + ng) * 2) =
                pack_bf2(acc[mf][nf][2] * rv0, acc[mf][nf][3] * rv1);
        }
    }
}

// ============================================================
// Kernel 4: mma.sync bf16 aggregate (v4: BK=128, 3x64KB stages)
//   out[ab][m][d] = relu( rinv[m] * sum_n adjT[m][n]*yT[ab][d][n] + bias[d] )
// CTA 128m x 128d, 16 warps (4m x 4d), warp 32x32, 512 threads.
// Chunk = 128 n, stored as two 16KB sub-tiles (row=128B swizzle atom).
// grid (16 m-tiles, 16 ab), 192KB smem.
// ============================================================
#define SUB_B     (128 * 128)          // 16 KB sub-tile
#define AGTILE_B  (2 * SUB_B)          // A per stage = 32 KB
#define STAGE_B   (2 * AGTILE_B)       // A + B per stage = 64 KB
#define NSTAGES   3
#define NCHUNKS   16                   // 2048 / 128

__global__ void __launch_bounds__(512, 1)
aggregate_mma(const float* __restrict__ bias, float* __restrict__ out) {
    extern __shared__ char smem_raw[];
    const uint32_t sbase = (smem_u32(smem_raw) + 127) & ~127u;

    const int tid  = threadIdx.x;
    const int wid  = tid >> 5;
    const int lane = tid & 31;
    const int warp_m = (wid & 3) * 32;
    const int warp_d = (wid >> 2) * 32;
    const int m0   = blockIdx.x * 128;
    const int ab   = blockIdx.y;

    const char* Ag = (const char*)(g_adjT + (size_t)m0 * NN);
    const char* Bg = (const char*)(g_yT + (size_t)ab * DOUT * NN);

    const int lrow = tid >> 2;          // 0..127
    const int lc0  = (tid & 3) * 2;

    auto load_buf = [&](int buf, int c) {
        const uint32_t Ao = sbase + buf * STAGE_B;
        const uint32_t Bo = Ao + AGTILE_B;
        const size_t rowbase = (size_t)lrow * NN + (size_t)c * 128;
#pragma unroll
        for (int s = 0; s < 2; ++s) {
#pragma unroll
            for (int i = 0; i < 2; ++i) {
                int ch = lc0 + i;
                uint32_t sw = (uint32_t)(ch ^ (lrow & 7)) * 16 + (uint32_t)lrow * 128;
                const size_t goff = (rowbase + s * 64 + ch * 8) * 2;
                cp_async16(Ao + s * SUB_B + sw, Ag + goff);
                cp_async16(Bo + s * SUB_B + sw, Bg + goff);
            }
        }
        cp_commit();
    };

    float acc[2][4][4];
#pragma unroll
    for (int mf = 0; mf < 2; ++mf)
#pragma unroll
        for (int nf = 0; nf < 4; ++nf)
#pragma unroll
            for (int e = 0; e < 4; ++e) acc[mf][nf][e] = 0.f;

    load_buf(0, 0);
    load_buf(1, 1);

    const int portion = lane >> 3;
    const int w8 = lane & 7;

    uint32_t afr[2][2][4], bfr[2][4][2];

    for (int c = 0; c < NCHUNKS; ++c) {
        if (c + 1 < NCHUNKS) cp_wait<1>(); else cp_wait<0>();
        __syncthreads();
        if (c + 2 < NCHUNKS) load_buf((c + 2) % NSTAGES, c + 2);

        const uint32_t Ao = sbase + (c % NSTAGES) * STAGE_B;
        const uint32_t Bo = Ao + AGTILE_B;

        auto ldfrag = [&](int ks, uint32_t (&a)[2][4], uint32_t (&b)[4][2]) {
            const int sub = ks >> 2;
            const int kb8 = (ks & 3) * 2;
            const uint32_t As = Ao + sub * SUB_B;
            const uint32_t Bs = Bo + sub * SUB_B;
#pragma unroll
            for (int mf = 0; mf < 2; ++mf) {
                int row = warp_m + mf * 16 + (portion & 1) * 8 + w8;
                int ch  = kb8 + (portion >> 1);
                ldsm_x4(a[mf], As + (uint32_t)row * 128 + (uint32_t)(ch ^ (row & 7)) * 16);
            }
#pragma unroll
            for (int nfp = 0; nfp < 2; ++nfp) {
                int row = warp_d + nfp * 16 + (portion >> 1) * 8 + w8;
                int ch  = kb8 + (portion & 1);
                uint32_t r[4];
                ldsm_x4(r, Bs + (uint32_t)row * 128 + (uint32_t)(ch ^ (row & 7)) * 16);
                b[2 * nfp][0]     = r[0];
                b[2 * nfp][1]     = r[1];
                b[2 * nfp + 1][0] = r[2];
                b[2 * nfp + 1][1] = r[3];
            }
        };

        ldfrag(0, afr[0], bfr[0]);
#pragma unroll
        for (int ks = 0; ks < 8; ++ks) {
            const int cur = ks & 1;
            if (ks < 7) ldfrag(ks + 1, afr[cur ^ 1], bfr[cur ^ 1]);
#pragma unroll
            for (int mf = 0; mf < 2; ++mf)
#pragma unroll
                for (int nf = 0; nf < 4; ++nf)
                    mma16816(acc[mf][nf], afr[cur][mf], bfr[cur][nf]);
        }
    }

    const int g  = lane >> 2;
    const int tc = lane & 3;
    float* outab = out + (size_t)ab * NN * DOUT;
#pragma unroll
    for (int mf = 0; mf < 2; ++mf) {
        const int mrow0 = m0 + warp_m + mf * 16 + g;
        const float rv0 = g_rinv[mrow0];
        const float rv1 = g_rinv[mrow0 + 8];
#pragma unroll
        for (int nf = 0; nf < 4; ++nf) {
            const int d0 = warp_d + nf * 8 + tc * 2;
            const float b0 = __ldg(&bias[d0]);
            const float b1 = __ldg(&bias[d0 + 1]);
            float2 v0, v1;
            v0.x = fmaxf(fmaf(acc[mf][nf][0], rv0, b0), 0.f);
            v0.y = fmaxf(fmaf(acc[mf][nf][1], rv0, b1), 0.f);
            v1.x = fmaxf(fmaf(acc[mf][nf][2], rv1, b0), 0.f);
            v1.y = fmaxf(fmaf(acc[mf][nf][3], rv1, b1), 0.f);
            *(float2*)&outab[(size_t)mrow0 * DOUT + d0]       = v0;
            *(float2*)&outab[(size_t)(mrow0 + 8) * DOUT + d0] = v1;
        }
    }
}

// ============================================================
extern "C" void kernel_launch(void* const* d_in, const int* in_sizes, int n_in,
                              void* d_out, int out_size) {
    const float* adj  = (const float*)d_in[0];
    const float* x    = (const float*)d_in[1];
    const float* w    = (const float*)d_in[2];
    const float* bias = (const float*)d_in[3];
    float* out        = (float*)d_out;

    const int agg_smem  = NSTAGES * STAGE_B + 256;            // 192 KB + slack
    const int proj_smem = 2 * PA_CH_B + 2 * PB_CH_B + 256;    // 48 KB + slack
    cudaFuncSetAttribute(aggregate_mma, cudaFuncAttributeMaxDynamicSharedMemorySize, agg_smem);
    cudaFuncSetAttribute(project_mma, cudaFuncAttributeMaxDynamicSharedMemorySize, proj_smem);

    transpose_colsum_kernel<<<dim3(32, 32), 256>>>(adj);
    rinv_kernel<<<NN / 256, 256>>>();
    convx_kernel<<<CONVX_BLOCKS + 8, 256>>>(x, w);
    project_mma<<<dim3(16, 16, 2), 256, proj_smem>>>();
    aggregate_mma<<<dim3(16, 16), 512, agg_smem>>>(bias, out);
}

// round 10
// speedup vs baseline: 1.0917x; 1.0448x over previous
#include <cuda_runtime.h>
#include <cuda_bf16.h>
#include <cstdint>

// dims fixed by setup_inputs
#define NN     2048
#define ABATCH 16
#define DIN    128
#define DOUT   128
#define TCHUNKS 32

// ---------------- device scratch (no allocs allowed) ----------------
__device__ float g_part[TCHUNKS * NN];
__device__ float g_rinv[NN];
__device__ __nv_bfloat16 g_adjT[(size_t)NN * NN];           // adjT[m][n], 8 MB
__device__ __nv_bfloat16 g_yT[(size_t)ABATCH * DOUT * NN];  // yT[ab][d][n], 8 MB
__device__ __nv_bfloat16 g_wt[DOUT * DIN];                  // WT[d][k] bf16

__device__ __forceinline__ uint32_t smem_u32(const void* p) {
    return (uint32_t)__cvta_generic_to_shared(p);
}
__device__ __forceinline__ void cp_async16(uint32_t dst, const void* src) {
    asm volatile("cp.async.cg.shared.global [%0], [%1], 16;" :: "r"(dst), "l"(src));
}
__device__ __forceinline__ void cp_commit() {
    asm volatile("cp.async.commit_group;" ::: "memory");
}
template <int N>
__device__ __forceinline__ void cp_wait() {
    asm volatile("cp.async.wait_group %0;" :: "n"(N) : "memory");
}
__device__ __forceinline__ void ldsm_x4(uint32_t* r, uint32_t addr) {
    asm volatile("ldmatrix.sync.aligned.m8n8.x4.shared.b16 {%0,%1,%2,%3}, [%4];"
                 : "=r"(r[0]), "=r"(r[1]), "=r"(r[2]), "=r"(r[3]) : "r"(addr));
}
__device__ __forceinline__ void mma16816(float* d, const uint32_t* a, const uint32_t* b) {
    asm volatile(
        "mma.sync.aligned.m16n8k16.row.col.f32.bf16.bf16.f32 "
        "{%0,%1,%2,%3}, {%4,%5,%6,%7}, {%8,%9}, {%0,%1,%2,%3};"
        : "+f"(d[0]), "+f"(d[1]), "+f"(d[2]), "+f"(d[3])
        : "r"(a[0]), "r"(a[1]), "r"(a[2]), "r"(a[3]), "r"(b[0]), "r"(b[1]));
}
__device__ __forceinline__ uint32_t pack_bf2(float a, float b) {
    __nv_bfloat162 t = __floats2bfloat162_rn(a, b);
    return *(uint32_t*)&t;
}

// ============================================================
// Kernel 1: fused transpose + partial column sums (64x64 tiles)
// ============================================================
__global__ void __launch_bounds__(256) transpose_colsum_kernel(const float* __restrict__ adj) {
    __shared__ float t[64][65];
    const int mx = blockIdx.x * 64, ny = blockIdx.y * 64;
    const int tid = threadIdx.x;
    const int row = tid >> 2;
    const int q   = tid & 3;

#pragma unroll
    for (int i = 0; i < 4; ++i) {
        const int f4 = q + 4 * i;
        float4 v = *(const float4*)&adj[(size_t)(ny + row) * NN + mx + f4 * 4];
        t[row][f4 * 4 + 0] = v.x;
        t[row][f4 * 4 + 1] = v.y;
        t[row][f4 * 4 + 2] = v.z;
        t[row][f4 * 4 + 3] = v.w;
    }
    __syncthreads();

    const int m  = row;
    const int nq = q * 16;
    float vv[16];
    float s = 0.f;
#pragma unroll
    for (int j = 0; j < 16; ++j) {
        vv[j] = t[nq + j][m];
        s += vv[j];
    }
    uint4 p0, p1;
    p0.x = pack_bf2(vv[0],  vv[1]);  p0.y = pack_bf2(vv[2],  vv[3]);
    p0.z = pack_bf2(vv[4],  vv[5]);  p0.w = pack_bf2(vv[6],  vv[7]);
    p1.x = pack_bf2(vv[8],  vv[9]);  p1.y = pack_bf2(vv[10], vv[11]);
    p1.z = pack_bf2(vv[12], vv[13]); p1.w = pack_bf2(vv[14], vv[15]);
    char* dst = (char*)g_adjT + ((size_t)(mx + m) * NN + ny + nq) * 2;
    *(uint4*)dst        = p0;
    *(uint4*)(dst + 16) = p1;

    s += __shfl_xor_sync(0xFFFFFFFF, s, 1);
    s += __shfl_xor_sync(0xFFFFFFFF, s, 2);
    if (q == 0) g_part[blockIdx.y * NN + mx + m] = s;
}

// ============================================================
// Kernel 2: blocks 0-7: rinv = rsqrt(colsum); blocks 8-15: WT[d][k]=bf16(W[k][d])
// grid 16 blocks x 256 threads
// ============================================================
__global__ void rinv_wt_kernel(const float* __restrict__ w) {
    if (blockIdx.x < 8) {
        int col = blockIdx.x * 256 + threadIdx.x;
        float s = 0.f;
#pragma unroll
        for (int c = 0; c < TCHUNKS; ++c)
            s += g_part[c * NN + col];
        g_rinv[col] = rsqrtf(s);
    } else {
        int idx = ((blockIdx.x - 8) * 256 + threadIdx.x) * 8;   // 8 blocks cover 16384
        int d  = idx >> 7;
        int k0 = idx & 127;
        uint4 pk;
        float a0 = w[(size_t)(k0 + 0) * DOUT + d], a1 = w[(size_t)(k0 + 1) * DOUT + d];
        float a2 = w[(size_t)(k0 + 2) * DOUT + d], a3 = w[(size_t)(k0 + 3) * DOUT + d];
        float a4 = w[(size_t)(k0 + 4) * DOUT + d], a5 = w[(size_t)(k0 + 5) * DOUT + d];
        float a6 = w[(size_t)(k0 + 6) * DOUT + d], a7 = w[(size_t)(k0 + 7) * DOUT + d];
        pk.x = pack_bf2(a0, a1);
        pk.y = pack_bf2(a2, a3);
        pk.z = pack_bf2(a4, a5);
        pk.w = pack_bf2(a6, a7);
        *(uint4*)((char*)g_wt + (size_t)idx * 2) = pk;
    }
}

// ============================================================
// Kernel 3: fused convert+projection via mma.sync
//   yT[ab][d][n] = bf16( rinv[n] * sum_k WT[d][k] * bf16(x[ab][n][k]) )
// x loaded fp32 directly from global (coalesced float4), converted in
// registers, stored into swizzled bf16 smem B tiles. WT via cp.async.
// CTA: 128d x 128n, 512 threads, 16 warps (4d x 4n), warp tile 32x32.
// grid (16 n-tiles, 16 ab).
// ============================================================
#define PTILE_B (128 * 128)   // one 64-k chunk tile: 128 rows x 128B = 16 KB

__global__ void __launch_bounds__(512, 1)
project_mma(const float* __restrict__ x) {
    extern __shared__ char smem_raw[];
    const uint32_t sbase = (smem_u32(smem_raw) + 127) & ~127u;
    const uint32_t Ao0 = sbase;                  // WT chunks: 2 x 16KB
    const uint32_t Bo0 = sbase + 2 * PTILE_B;    // x-bf16 chunks: 2 x 16KB

    const int tid  = threadIdx.x;
    const int wid  = tid >> 5;
    const int lane = tid & 31;
    const int warp_m = (wid & 3) * 32;     // d
    const int warp_d = (wid >> 2) * 32;    // n (local)
    const int n0 = blockIdx.x * 128;
    const int ab = blockIdx.y;

    // WT via cp.async into swizzled A tiles
    {
        const char* Ag = (const char*)g_wt;
        const int lrow = tid >> 2;          // 0..127
        const int lc0  = (tid & 3) * 2;
#pragma unroll
        for (int c = 0; c < 2; ++c)
#pragma unroll
            for (int i = 0; i < 2; ++i) {
                int ch = lc0 + i;
                uint32_t sw = (uint32_t)(ch ^ (lrow & 7)) * 16 + (uint32_t)lrow * 128;
                size_t goff = ((size_t)lrow * DIN + c * 64 + ch * 8) * 2;
                cp_async16(Ao0 + c * PTILE_B + sw, Ag + goff);
            }
        cp_commit();
    }

    // x fp32 -> bf16 swizzled B tiles, in registers.
    // idx = tid + i*512: row = idx>>5 (warp-uniform), f4c = idx&31.
    // k = f4c*4..+3; chunk = f4c>>4; 16B-unit ku = (f4c&15)>>1; half = f4c&1.
    {
        const float* xab = x + ((size_t)ab * NN + n0) * DIN;
        const int f4c = tid & 31;
        const int chunk = f4c >> 4;
        const int ku    = (f4c & 15) >> 1;
        const int half  = f4c & 1;
#pragma unroll
        for (int i = 0; i < 8; ++i) {
            const int row = (tid >> 5) + i * 16;
            float4 v = *(const float4*)&xab[(size_t)row * DIN + f4c * 4];
            uint32_t lo = pack_bf2(v.x, v.y);
            uint32_t hi = pack_bf2(v.z, v.w);
            uint32_t addr = Bo0 + chunk * PTILE_B + (uint32_t)row * 128
                          + (uint32_t)(ku ^ (row & 7)) * 16 + half * 8;
            asm volatile("st.shared.v2.b32 [%0], {%1, %2};" :: "r"(addr), "r"(lo), "r"(hi));
        }
    }
    cp_wait<0>();
    __syncthreads();

    float acc[2][4][4];
#pragma unroll
    for (int mf = 0; mf < 2; ++mf)
#pragma unroll
        for (int nf = 0; nf < 4; ++nf)
#pragma unroll
            for (int e = 0; e < 4; ++e) acc[mf][nf][e] = 0.f;

    const int portion = lane >> 3;
    const int w8 = lane & 7;

#pragma unroll
    for (int c = 0; c < 2; ++c) {
        const uint32_t Ao = Ao0 + c * PTILE_B;
        const uint32_t Bo = Bo0 + c * PTILE_B;
#pragma unroll
        for (int ks = 0; ks < 4; ++ks) {
            const int kb8 = ks * 2;
            uint32_t a[2][4], b[4][2];
#pragma unroll
            for (int mf = 0; mf < 2; ++mf) {
                int row = warp_m + mf * 16 + (portion & 1) * 8 + w8;
                int ch  = kb8 + (portion >> 1);
                ldsm_x4(a[mf], Ao + (uint32_t)row * 128 + (uint32_t)(ch ^ (row & 7)) * 16);
            }
#pragma unroll
            for (int nfp = 0; nfp < 2; ++nfp) {
                int row = warp_d + nfp * 16 + (portion >> 1) * 8 + w8;
                int ch  = kb8 + (portion & 1);
                uint32_t r[4];
                ldsm_x4(r, Bo + (uint32_t)row * 128 + (uint32_t)(ch ^ (row & 7)) * 16);
                b[2 * nfp][0]     = r[0];
                b[2 * nfp][1]     = r[1];
                b[2 * nfp + 1][0] = r[2];
                b[2 * nfp + 1][1] = r[3];
            }
#pragma unroll
            for (int mf = 0; mf < 2; ++mf)
#pragma unroll
                for (int nf = 0; nf < 4; ++nf)
                    mma16816(acc[mf][nf], a[mf], b[nf]);
        }
    }

    const int g  = lane >> 2;
    const int tc = lane & 3;
    char* yT = (char*)(g_yT + (size_t)ab * DOUT * NN);
#pragma unroll
    for (int mf = 0; mf < 2; ++mf) {
        const int d0g = warp_m + mf * 16 + g;
#pragma unroll
        for (int nf = 0; nf < 4; ++nf) {
            const int ng = n0 + warp_d + nf * 8 + tc * 2;
            const float rv0 = g_rinv[ng];
            const float rv1 = g_rinv[ng + 1];
            *(uint32_t*)(yT + ((size_t)d0g * NN + ng) * 2) =
                pack_bf2(acc[mf][nf][0] * rv0, acc[mf][nf][1] * rv1);
            *(uint32_t*)(yT + ((size_t)(d0g + 8) * NN + ng) * 2) =
                pack_bf2(acc[mf][nf][2] * rv0, acc[mf][nf][3] * rv1);
        }
    }
}

// ============================================================
// Kernel 4: mma.sync bf16 aggregate (BK=128, 3x64KB stages)
//   out[ab][m][d] = relu( rinv[m] * sum_n adjT[m][n]*yT[ab][d][n] + bias[d] )
// CTA 128m x 128d, 16 warps (4m x 4d), warp 32x32, 512 threads.
// grid (16 m-tiles, 16 ab), 192KB smem.
// ============================================================
#define SUB_B     (128 * 128)          // 16 KB sub-tile
#define AGTILE_B  (2 * SUB_B)          // A per stage = 32 KB
#define STAGE_B   (2 * AGTILE_B)       // A + B per stage = 64 KB
#define NSTAGES   3
#define NCHUNKS   16                   // 2048 / 128

__global__ void __launch_bounds__(512, 1)
aggregate_mma(const float* __restrict__ bias, float* __restrict__ out) {
    extern __shared__ char smem_raw[];
    const uint32_t sbase = (smem_u32(smem_raw) + 127) & ~127u;

    const int tid  = threadIdx.x;
    const int wid  = tid >> 5;
    const int lane = tid & 31;
    const int warp_m = (wid & 3) * 32;
    const int warp_d = (wid >> 2) * 32;
    const int m0   = blockIdx.x * 128;
    const int ab   = blockIdx.y;

    const char* Ag = (const char*)(g_adjT + (size_t)m0 * NN);
    const char* Bg = (const char*)(g_yT + (size_t)ab * DOUT * NN);

    const int lrow = tid >> 2;          // 0..127
    const int lc0  = (tid & 3) * 2;

    auto load_buf = [&](int buf, int c) {
        const uint32_t Ao = sbase + buf * STAGE_B;
        const uint32_t Bo = Ao + AGTILE_B;
        const size_t rowbase = (size_t)lrow * NN + (size_t)c * 128;
#pragma unroll
        for (int s = 0; s < 2; ++s) {
#pragma unroll
            for (int i = 0; i < 2; ++i) {
                int ch = lc0 + i;
                uint32_t sw = (uint32_t)(ch ^ (lrow & 7)) * 16 + (uint32_t)lrow * 128;
                const size_t goff = (rowbase + s * 64 + ch * 8) * 2;
                cp_async16(Ao + s * SUB_B + sw, Ag + goff);
                cp_async16(Bo + s * SUB_B + sw, Bg + goff);
            }
        }
        cp_commit();
    };

    float acc[2][4][4];
#pragma unroll
    for (int mf = 0; mf < 2; ++mf)
#pragma unroll
        for (int nf = 0; nf < 4; ++nf)
#pragma unroll
            for (int e = 0; e < 4; ++e) acc[mf][nf][e] = 0.f;

    load_buf(0, 0);
    load_buf(1, 1);

    const int portion = lane >> 3;
    const int w8 = lane & 7;

    uint32_t afr[2][2][4], bfr[2][4][2];

    for (int c = 0; c < NCHUNKS; ++c) {
        if (c + 1 < NCHUNKS) cp_wait<1>(); else cp_wait<0>();
        __syncthreads();
        if (c + 2 < NCHUNKS) load_buf((c + 2) % NSTAGES, c + 2);

        const uint32_t Ao = sbase + (c % NSTAGES) * STAGE_B;
        const uint32_t Bo = Ao + AGTILE_B;

        auto ldfrag = [&](int ks, uint32_t (&a)[2][4], uint32_t (&b)[4][2]) {
            const int sub = ks >> 2;
            const int kb8 = (ks & 3) * 2;
            const uint32_t As = Ao + sub * SUB_B;
            const uint32_t Bs = Bo + sub * SUB_B;
#pragma unroll
            for (int mf = 0; mf < 2; ++mf) {
                int row = warp_m + mf * 16 + (portion & 1) * 8 + w8;
                int ch  = kb8 + (portion >> 1);
                ldsm_x4(a[mf], As + (uint32_t)row * 128 + (uint32_t)(ch ^ (row & 7)) * 16);
            }
#pragma unroll
            for (int nfp = 0; nfp < 2; ++nfp) {
                int row = warp_d + nfp * 16 + (portion >> 1) * 8 + w8;
                int ch  = kb8 + (portion & 1);
                uint32_t r[4];
                ldsm_x4(r, Bs + (uint32_t)row * 128 + (uint32_t)(ch ^ (row & 7)) * 16);
                b[2 * nfp][0]     = r[0];
                b[2 * nfp][1]     = r[1];
                b[2 * nfp + 1][0] = r[2];
                b[2 * nfp + 1][1] = r[3];
            }
        };

        ldfrag(0, afr[0], bfr[0]);
#pragma unroll
        for (int ks = 0; ks < 8; ++ks) {
            const int cur = ks & 1;
            if (ks < 7) ldfrag(ks + 1, afr[cur ^ 1], bfr[cur ^ 1]);
#pragma unroll
            for (int mf = 0; mf < 2; ++mf)
#pragma unroll
                for (int nf = 0; nf < 4; ++nf)
                    mma16816(acc[mf][nf], afr[cur][mf], bfr[cur][nf]);
        }
    }

    const int g  = lane >> 2;
    const int tc = lane & 3;
    float* outab = out + (size_t)ab * NN * DOUT;
#pragma unroll
    for (int mf = 0; mf < 2; ++mf) {
        const int mrow0 = m0 + warp_m + mf * 16 + g;
        const float rv0 = g_rinv[mrow0];
        const float rv1 = g_rinv[mrow0 + 8];
#pragma unroll
        for (int nf = 0; nf < 4; ++nf) {
            const int d0 = warp_d + nf * 8 + tc * 2;
            const float b0 = __ldg(&bias[d0]);
            const float b1 = __ldg(&bias[d0 + 1]);
            float2 v0, v1;
            v0.x = fmaxf(fmaf(acc[mf][nf][0], rv0, b0), 0.f);
            v0.y = fmaxf(fmaf(acc[mf][nf][1], rv0, b1), 0.f);
            v1.x = fmaxf(fmaf(acc[mf][nf][2], rv1, b0), 0.f);
            v1.y = fmaxf(fmaf(acc[mf][nf][3], rv1, b1), 0.f);
            *(float2*)&outab[(size_t)mrow0 * DOUT + d0]       = v0;
            *(float2*)&outab[(size_t)(mrow0 + 8) * DOUT + d0] = v1;
        }
    }
}

// ============================================================
extern "C" void kernel_launch(void* const* d_in, const int* in_sizes, int n_in,
                              void* d_out, int out_size) {
    const float* adj  = (const float*)d_in[0];
    const float* x    = (const float*)d_in[1];
    const float* w    = (const float*)d_in[2];
    const float* bias = (const float*)d_in[3];
    float* out        = (float*)d_out;

    const int agg_smem  = NSTAGES * STAGE_B + 256;   // 192 KB + slack
    const int proj_smem = 4 * PTILE_B + 256;         // 64 KB + slack
    cudaFuncSetAttribute(aggregate_mma, cudaFuncAttributeMaxDynamicSharedMemorySize, agg_smem);
    cudaFuncSetAttribute(project_mma, cudaFuncAttributeMaxDynamicSharedMemorySize, proj_smem);

    transpose_colsum_kernel<<<dim3(32, 32), 256>>>(adj);
    rinv_wt_kernel<<<16, 256>>>(w);
    project_mma<<<dim3(16, 16), 512, proj_smem>>>(x);
    aggregate_mma<<<dim3(16, 16), 512, agg_smem>>>(bias, out);
}